// round 15
// baseline (speedup 1.0000x reference)
#include <cuda_runtime.h>
#include <cuda_bf16.h>
#include <cstdint>

#define D 128
#define MAXN 100000
#define MAXE 1600000

// Scratch (static device globals — no allocation at launch time)
__device__ float g_h[(size_t)MAXN * D];     // layer-1 dinv-scaled GEMM output
__device__ float g_h2[(size_t)MAXN * D];    // layer-2 dinv-scaled GEMM output
__device__ float g_dinv[MAXN];
__device__ int   g_deg[MAXN];
__device__ int   g_off[MAXN];               // CSR offsets (exclusive scan of deg)
__device__ int   g_cursor[MAXN];            // fill cursors
__device__ int   g_src[MAXE];               // CSR: source node per incoming edge
__device__ int   g_bsum[128];               // scan block sums
__device__ int   g_bbase[128];              // scan block bases
__device__ float2 g_wpack[2][16 * 4 * D];   // pre-rounded, pre-packed W1/W2

__device__ __forceinline__ uint32_t f2tf32(float v) {
    uint32_t u;
    asm("cvt.rna.tf32.f32 %0, %1;" : "=r"(u) : "f"(v));
    return u;
}

// ---------------------------------------------------------------------------
__global__ void count_deg_kernel(const int* __restrict__ col, int E) {
    int e = blockIdx.x * blockDim.x + threadIdx.x;
    if (e < E) atomicAdd(&g_deg[col[e]], 1);
}

// Pre-pack W: RNA-round to tf32 and pack (k, k+4) pairs.
__global__ void pack_w_kernel(const float* __restrict__ W1,
                              const float* __restrict__ W2) {
    int idx = blockIdx.x * blockDim.x + threadIdx.x;   // 0 .. 2*8192-1
    int w   = idx >> 13;
    int p   = idx & 8191;
    int ks  = p >> 9;
    int rem = p & 511;
    int tg  = rem >> 7, c = rem & 127;
    int k   = ks * 8 + tg;
    const float* W = w ? W2 : W1;
    float2 v;
    v.x = __uint_as_float(f2tf32(W[k * D + c]));
    v.y = __uint_as_float(f2tf32(W[(k + 4) * D + c]));
    g_wpack[w][p] = v;
}

// ---------------------------------------------------------------------------
// Exclusive scan of g_deg -> g_off (+ fused dinv computation)
// ---------------------------------------------------------------------------
__global__ __launch_bounds__(1024) void scan1_kernel(int n) {
    __shared__ int s[1024];
    int t = threadIdx.x;
    int i = blockIdx.x * 1024 + t;
    int v = (i < n) ? g_deg[i] : 0;
    if (i < n) g_dinv[i] = rsqrtf((float)v + 1.0f);
    s[t] = v;
    __syncthreads();
#pragma unroll
    for (int off = 1; off < 1024; off <<= 1) {
        int a = (t >= off) ? s[t - off] : 0;
        __syncthreads();
        s[t] += a;
        __syncthreads();
    }
    if (i < n) g_off[i] = s[t] - v;          // exclusive
    if (t == 1023) g_bsum[blockIdx.x] = s[1023];
}

__global__ void scan2_kernel(int nb) {
    __shared__ int s[128];
    int t = threadIdx.x;
    int v = (t < nb) ? g_bsum[t] : 0;
    s[t] = v;
    __syncthreads();
#pragma unroll
    for (int off = 1; off < 128; off <<= 1) {
        int a = (t >= off) ? s[t - off] : 0;
        __syncthreads();
        s[t] += a;
        __syncthreads();
    }
    g_bbase[t] = s[t] - v;                   // exclusive
}

__global__ __launch_bounds__(1024) void scan3_kernel(int n) {
    int i = blockIdx.x * 1024 + threadIdx.x;
    if (i < n) {
        int o = g_off[i] + g_bbase[blockIdx.x];
        g_off[i] = o;
        g_cursor[i] = o;
    }
}

__global__ void fill_kernel(const int* __restrict__ row,
                            const int* __restrict__ col, int E) {
    int e = blockIdx.x * blockDim.x + threadIdx.x;
    if (e < E) {
        int p = atomicAdd(&g_cursor[col[e]], 1);
        g_src[p] = row[e];
    }
}

// ---------------------------------------------------------------------------
// Shared GEMM core: 512 threads, tile 128 rows x 128 cols.
// Warp grid 8x2: warp computes 16 rows x 64 cols via mma.m16n8k8.tf32.
// X smem: [128][132] floats. W smem: packed (k,k+4) float2 [64][132].
// ---------------------------------------------------------------------------
#define XS_STRIDE 132
#define WSP_STRIDE 132
#define GEMM_SMEM_BYTES (128 * XS_STRIDE * 4 + 16 * 4 * WSP_STRIDE * 8)

// MMA mainloop + dinv epilogue (xs holds tf32 bits of the 128x128 input tile)
__device__ __forceinline__ void mma_tile_and_store(
    const float* xs, const float2* wsp, float* __restrict__ Y,
    int row0, int n, int lane, int wid) {
    const int warp_m = wid >> 1;               // 0..7 -> rows warp_m*16
    const int warp_n = wid & 1;                // 0..1 -> cols warp_n*64
    const int gid    = lane >> 2;              // 0..7
    const int tig    = lane & 3;               // 0..3

    float acc[8][4];
#pragma unroll
    for (int j = 0; j < 8; ++j)
#pragma unroll
        for (int q = 0; q < 4; ++q) acc[j][q] = 0.0f;

    const float* xb = xs + (warp_m * 16 + gid) * XS_STRIDE + tig;

#pragma unroll
    for (int ks = 0; ks < 16; ++ks) {
        const int k0 = ks * 8;
        uint32_t a0 = __float_as_uint(xb[k0]);
        uint32_t a1 = __float_as_uint(xb[8 * XS_STRIDE + k0]);
        uint32_t a2 = __float_as_uint(xb[k0 + 4]);
        uint32_t a3 = __float_as_uint(xb[8 * XS_STRIDE + k0 + 4]);
        const float2* wrow = wsp + (ks * 4 + tig) * WSP_STRIDE + warp_n * 64 + gid;
#pragma unroll
        for (int j = 0; j < 8; ++j) {
            float2 b = wrow[j * 8];
            asm volatile(
                "mma.sync.aligned.m16n8k8.row.col.f32.tf32.tf32.f32 "
                "{%0,%1,%2,%3}, {%4,%5,%6,%7}, {%8,%9}, {%0,%1,%2,%3};"
                : "+f"(acc[j][0]), "+f"(acc[j][1]), "+f"(acc[j][2]), "+f"(acc[j][3])
                : "r"(a0), "r"(a1), "r"(a2), "r"(a3),
                  "r"(__float_as_uint(b.x)), "r"(__float_as_uint(b.y)));
        }
    }

    int rA = row0 + warp_m * 16 + gid;
    int rB = rA + 8;
    int cb = warp_n * 64 + tig * 2;
    float sA = (rA < n) ? g_dinv[rA] : 0.0f;
    float sB = (rB < n) ? g_dinv[rB] : 0.0f;
#pragma unroll
    for (int j = 0; j < 8; ++j) {
        int c = cb + j * 8;
        if (rA < n) *(float2*)&Y[(size_t)rA * D + c] =
            make_float2(acc[j][0] * sA, acc[j][1] * sA);
        if (rB < n) *(float2*)&Y[(size_t)rB * D + c] =
            make_float2(acc[j][2] * sB, acc[j][3] * sB);
    }
}

// ---------------------------------------------------------------------------
// Layer-1 GEMM: Y[r,:] = dinv[r] * (X[r,:] @ W1)
// ---------------------------------------------------------------------------
__global__ __launch_bounds__(512) void gemm_tf32_kernel(
    const float* __restrict__ X, const float2* __restrict__ Wp,
    float* __restrict__ Y, int n) {
    extern __shared__ float smem[];
    float*  xs  = smem;                               // [128][132]
    float2* wsp = (float2*)(smem + 128 * XS_STRIDE);  // [64][132]

    const int t    = threadIdx.x;
    const int row0 = blockIdx.x * 128;

    // Copy pre-packed W (8192 float2)
#pragma unroll
    for (int i = 0; i < 16; ++i) {
        int idx = i * 512 + t;
        int r = idx >> 7, c = idx & 127;
        wsp[r * WSP_STRIDE + c] = Wp[idx];
    }
    // Load X tile (128 x 128), RNA-round to tf32 bits
#pragma unroll
    for (int i = 0; i < 32; ++i) {
        int idx = i * 512 + t;
        int r = idx >> 7, c = idx & 127;
        float v = (row0 + r < n) ? X[(size_t)(row0 + r) * D + c] : 0.0f;
        xs[r * XS_STRIDE + c] = __uint_as_float(f2tf32(v));
    }
    __syncthreads();

    mma_tile_and_store(xs, wsp, Y, row0, n, t & 31, t >> 5);
}

// ---------------------------------------------------------------------------
// Fused gather(layer1) + bias + relu + GEMM(layer2):
//   g1 = dinv[c]*(sum_{r in in(c)} h[r] + h[c]) + b1
//   xs[c,:] = tf32(relu(g1));  Y = dinv .* (xs @ W2)
// NOTE: Y must NOT alias h (gather reads arbitrary h rows across blocks).
// ---------------------------------------------------------------------------
__global__ __launch_bounds__(512) void fused_gather_gemm_kernel(
    const float* __restrict__ h, const float* __restrict__ b1,
    const float2* __restrict__ Wp, float* __restrict__ Y, int n, int E) {
    extern __shared__ float smem[];
    float*  xs  = smem;                               // [128][132]
    float2* wsp = (float2*)(smem + 128 * XS_STRIDE);  // [64][132]

    const int t    = threadIdx.x;
    const int lane = t & 31;
    const int wid  = t >> 5;
    const int row0 = blockIdx.x * 128;

    // W copy first — independent of gather, hides under gather latency
#pragma unroll
    for (int i = 0; i < 16; ++i) {
        int idx = i * 512 + t;
        int r = idx >> 7, c = idx & 127;
        wsp[r * WSP_STRIDE + c] = Wp[idx];
    }

    const float4* h4 = (const float4*)h;
    float4 bv = ((const float4*)b1)[lane];

    // Gather phase: warp wid handles nodes row0 + wid*8 .. +7
#pragma unroll 1
    for (int i = 0; i < 8; ++i) {
        int lr   = wid * 8 + i;                // local row 0..127
        int node = row0 + lr;
        float4 acc = make_float4(0.f, 0.f, 0.f, 0.f);
        if (node < n) {
            float dc = g_dinv[node];
            int j    = g_off[node];
            int eend = (node + 1 < n) ? g_off[node + 1] : E;
            while (j < eend) {
                int cnt = min(32, eend - j);
                int r = 0;
                if (lane < cnt) r = g_src[j + lane];
#pragma unroll 4
                for (int k = 0; k < cnt; ++k) {
                    int rk = __shfl_sync(0xffffffffu, r, k);
                    float4 hv = h4[(size_t)rk * 32 + lane];
                    acc.x += hv.x;
                    acc.y += hv.y;
                    acc.z += hv.z;
                    acc.w += hv.w;
                }
                j += cnt;
            }
            float4 hv = h4[(size_t)node * 32 + lane];
            acc.x = fmaf(dc, acc.x + hv.x, bv.x);
            acc.y = fmaf(dc, acc.y + hv.y, bv.y);
            acc.z = fmaf(dc, acc.z + hv.z, bv.z);
            acc.w = fmaf(dc, acc.w + hv.w, bv.w);
        }
        // relu + tf32-round, store into GEMM input tile
        float* xr = xs + lr * XS_STRIDE + lane * 4;
        xr[0] = __uint_as_float(f2tf32(fmaxf(acc.x, 0.f)));
        xr[1] = __uint_as_float(f2tf32(fmaxf(acc.y, 0.f)));
        xr[2] = __uint_as_float(f2tf32(fmaxf(acc.z, 0.f)));
        xr[3] = __uint_as_float(f2tf32(fmaxf(acc.w, 0.f)));
    }
    __syncthreads();

    mma_tile_and_store(xs, wsp, Y, row0, n, lane, wid);
}

// ---------------------------------------------------------------------------
// Final gather (layer 2): out[c] = dinv[c]*(sum h2[r] + h2[c]) + b2
// ---------------------------------------------------------------------------
__global__ __launch_bounds__(256) void gather_kernel(
    const float* __restrict__ h, const float* __restrict__ b,
    float* __restrict__ out, int n, int E) {
    int node = blockIdx.x * 8 + (threadIdx.x >> 5);
    if (node >= n) return;
    int lane = threadIdx.x & 31;

    float dc = g_dinv[node];
    const float4* h4 = (const float4*)h;

    int j    = g_off[node];
    int eend = (node + 1 < n) ? g_off[node + 1] : E;

    float4 acc = make_float4(0.f, 0.f, 0.f, 0.f);

    while (j < eend) {
        int cnt = min(32, eend - j);
        int r = 0;
        if (lane < cnt) r = g_src[j + lane];
#pragma unroll 4
        for (int k = 0; k < cnt; ++k) {
            int rk = __shfl_sync(0xffffffffu, r, k);
            float4 hv = h4[(size_t)rk * 32 + lane];
            acc.x += hv.x;
            acc.y += hv.y;
            acc.z += hv.z;
            acc.w += hv.w;
        }
        j += cnt;
    }

    float4 hv = h4[(size_t)node * 32 + lane];
    float4 bv = ((const float4*)b)[lane];
    float4 o;
    o.x = fmaf(dc, acc.x + hv.x, bv.x);
    o.y = fmaf(dc, acc.y + hv.y, bv.y);
    o.z = fmaf(dc, acc.z + hv.z, bv.z);
    o.w = fmaf(dc, acc.w + hv.w, bv.w);
    ((float4*)out)[(size_t)node * 32 + lane] = o;
}

// ---------------------------------------------------------------------------
extern "C" void kernel_launch(void* const* d_in, const int* in_sizes, int n_in,
                              void* d_out, int out_size) {
    const float* x  = (const float*)d_in[0];
    const int*   ei = (const int*)d_in[1];
    const float* W1 = (const float*)d_in[2];
    const float* b1 = (const float*)d_in[3];
    const float* W2 = (const float*)d_in[4];
    const float* b2 = (const float*)d_in[5];
    float* out = (float*)d_out;

    int n = in_sizes[0] / D;
    int E = in_sizes[1] / 2;
    const int* row = ei;        // edge_index[0]
    const int* col = ei + E;    // edge_index[1]

    float* h;    cudaGetSymbolAddress((void**)&h,   g_h);
    float* h2;   cudaGetSymbolAddress((void**)&h2,  g_h2);
    float2* wp;  cudaGetSymbolAddress((void**)&wp,  g_wpack);
    int* degp;   cudaGetSymbolAddress((void**)&degp, g_deg);

    cudaFuncSetAttribute(gemm_tf32_kernel,
                         cudaFuncAttributeMaxDynamicSharedMemorySize,
                         GEMM_SMEM_BYTES);
    cudaFuncSetAttribute(fused_gather_gemm_kernel,
                         cudaFuncAttributeMaxDynamicSharedMemorySize,
                         GEMM_SMEM_BYTES);

    int eb256 = (E + 255) / 256;
    int nb1k  = (n + 1023) / 1024;
    int gblk  = (n + 127) / 128;
    int gath  = (n + 7) / 8;

    // normalization + CSR build + weight pre-pack (once per call)
    cudaMemsetAsync(degp, 0, (size_t)n * sizeof(int));
    count_deg_kernel<<<eb256, 256>>>(col, E);
    pack_w_kernel<<<64, 256>>>(W1, W2);
    scan1_kernel<<<nb1k, 1024>>>(n);     // also computes dinv
    scan2_kernel<<<1, 128>>>(nb1k);
    scan3_kernel<<<1024 <= n ? nb1k : 1, 1024>>>(n);
    fill_kernel<<<eb256, 256>>>(row, col, E);

    // layer 1 GEMM: h1 = dinv .* (x @ W1)
    gemm_tf32_kernel<<<gblk, 512, GEMM_SMEM_BYTES>>>(x, wp, h, n);

    // fused: gather1 + bias + relu + GEMM2 -> h2 = dinv .* (relu(g1) @ W2)
    // (writes to h2, distinct from gather source h)
    fused_gather_gemm_kernel<<<gblk, 512, GEMM_SMEM_BYTES>>>(
        h, b1, wp + 8192, h2, n, E);

    // final gather (layer 2)
    gather_kernel<<<gath, 256>>>(h2, b2, out, n, E);
}

// round 16
// speedup vs baseline: 1.4138x; 1.4138x over previous
#include <cuda_runtime.h>
#include <cuda_fp16.h>
#include <cstdint>

#define D 128
#define MAXN 100000
#define MAXE 1600000

// Scratch (static device globals — no allocation at launch time)
__device__ __half g_hA[(size_t)MAXN * D];   // layer-1 dinv-scaled GEMM out (fp16)
__device__ __half g_hB[(size_t)MAXN * D];   // layer-2 dinv-scaled GEMM out (fp16)
__device__ float  g_agg[(size_t)MAXN * D];  // gather1 output (fp32, GEMM2 input)
__device__ float  g_dinv[MAXN];
__device__ int    g_deg[MAXN];
__device__ int    g_off[MAXN];              // CSR offsets (exclusive scan of deg)
__device__ int    g_cursor[MAXN];           // fill cursors
__device__ int    g_src[MAXE];              // CSR: source node per incoming edge
__device__ int    g_bsum[128];              // scan block sums
__device__ int    g_bbase[128];             // scan block bases
__device__ float2 g_wpack[2][16 * 4 * D];   // pre-rounded, pre-packed W1/W2

__device__ __forceinline__ uint32_t f2tf32(float v) {
    uint32_t u;
    asm("cvt.rna.tf32.f32 %0, %1;" : "=r"(u) : "f"(v));
    return u;
}

// ---------------------------------------------------------------------------
__global__ void count_deg_kernel(const int* __restrict__ col, int E) {
    int e = blockIdx.x * blockDim.x + threadIdx.x;
    if (e < E) atomicAdd(&g_deg[col[e]], 1);
}

// Pre-pack W: RNA-round to tf32 and pack (k, k+4) pairs.
__global__ void pack_w_kernel(const float* __restrict__ W1,
                              const float* __restrict__ W2) {
    int idx = blockIdx.x * blockDim.x + threadIdx.x;   // 0 .. 2*8192-1
    int w   = idx >> 13;
    int p   = idx & 8191;
    int ks  = p >> 9;
    int rem = p & 511;
    int tg  = rem >> 7, c = rem & 127;
    int k   = ks * 8 + tg;
    const float* W = w ? W2 : W1;
    float2 v;
    v.x = __uint_as_float(f2tf32(W[k * D + c]));
    v.y = __uint_as_float(f2tf32(W[(k + 4) * D + c]));
    g_wpack[w][p] = v;
}

// ---------------------------------------------------------------------------
// Exclusive scan of g_deg -> g_off (+ fused dinv computation)
// ---------------------------------------------------------------------------
__global__ __launch_bounds__(1024) void scan1_kernel(int n) {
    __shared__ int s[1024];
    int t = threadIdx.x;
    int i = blockIdx.x * 1024 + t;
    int v = (i < n) ? g_deg[i] : 0;
    if (i < n) g_dinv[i] = rsqrtf((float)v + 1.0f);
    s[t] = v;
    __syncthreads();
#pragma unroll
    for (int off = 1; off < 1024; off <<= 1) {
        int a = (t >= off) ? s[t - off] : 0;
        __syncthreads();
        s[t] += a;
        __syncthreads();
    }
    if (i < n) g_off[i] = s[t] - v;          // exclusive
    if (t == 1023) g_bsum[blockIdx.x] = s[1023];
}

__global__ void scan2_kernel(int nb) {
    __shared__ int s[128];
    int t = threadIdx.x;
    int v = (t < nb) ? g_bsum[t] : 0;
    s[t] = v;
    __syncthreads();
#pragma unroll
    for (int off = 1; off < 128; off <<= 1) {
        int a = (t >= off) ? s[t - off] : 0;
        __syncthreads();
        s[t] += a;
        __syncthreads();
    }
    g_bbase[t] = s[t] - v;                   // exclusive
}

__global__ __launch_bounds__(1024) void scan3_kernel(int n) {
    int i = blockIdx.x * 1024 + threadIdx.x;
    if (i < n) {
        int o = g_off[i] + g_bbase[blockIdx.x];
        g_off[i] = o;
        g_cursor[i] = o;
    }
}

__global__ void fill_kernel(const int* __restrict__ row,
                            const int* __restrict__ col, int E) {
    int e = blockIdx.x * blockDim.x + threadIdx.x;
    if (e < E) {
        int p = atomicAdd(&g_cursor[col[e]], 1);
        g_src[p] = row[e];
    }
}

// ---------------------------------------------------------------------------
// tf32 tensor-core GEMM: Y[r,:] = (half) dinv[r] * (act(X[r,:]) @ W)
// 512 threads, tile 128 rows x 128 cols; warp grid 8x2, mma.m16n8k8.tf32.
// X smem: [128][132] floats. W smem: packed (k,k+4) float2 [64][132].
// Output stored fp16 (dinv-scaled) for cheap gathers.
// ---------------------------------------------------------------------------
#define XS_STRIDE 132
#define WSP_STRIDE 132
#define GEMM_SMEM_BYTES (128 * XS_STRIDE * 4 + 16 * 4 * WSP_STRIDE * 8)

__global__ __launch_bounds__(512) void gemm_tf32_kernel(
    const float* __restrict__ X, const float2* __restrict__ Wp,
    __half* __restrict__ Y, int n, int apply_relu) {
    extern __shared__ float smem[];
    float*  xs  = smem;                               // [128][132]
    float2* wsp = (float2*)(smem + 128 * XS_STRIDE);  // [64][132]

    const int t      = threadIdx.x;
    const int lane   = t & 31;
    const int wid    = t >> 5;
    const int warp_m = wid >> 1;               // 0..7 -> rows warp_m*16
    const int warp_n = wid & 1;                // 0..1 -> cols warp_n*64
    const int gid    = lane >> 2;              // 0..7
    const int tig    = lane & 3;               // 0..3
    const int row0   = blockIdx.x * 128;

    // Copy pre-packed W (8192 float2)
#pragma unroll
    for (int i = 0; i < 16; ++i) {
        int idx = i * 512 + t;
        int r = idx >> 7, c = idx & 127;
        wsp[r * WSP_STRIDE + c] = Wp[idx];
    }
    // Load X tile (128 x 128), optional relu, RNA-round to tf32 bits
#pragma unroll
    for (int i = 0; i < 32; ++i) {
        int idx = i * 512 + t;
        int r = idx >> 7, c = idx & 127;
        float v = (row0 + r < n) ? X[(size_t)(row0 + r) * D + c] : 0.0f;
        if (apply_relu) v = fmaxf(v, 0.0f);
        xs[r * XS_STRIDE + c] = __uint_as_float(f2tf32(v));
    }
    __syncthreads();

    float acc[8][4];
#pragma unroll
    for (int j = 0; j < 8; ++j)
#pragma unroll
        for (int q = 0; q < 4; ++q) acc[j][q] = 0.0f;

    const float* xb = xs + (warp_m * 16 + gid) * XS_STRIDE + tig;

#pragma unroll
    for (int ks = 0; ks < 16; ++ks) {
        const int k0 = ks * 8;
        uint32_t a0 = __float_as_uint(xb[k0]);
        uint32_t a1 = __float_as_uint(xb[8 * XS_STRIDE + k0]);
        uint32_t a2 = __float_as_uint(xb[k0 + 4]);
        uint32_t a3 = __float_as_uint(xb[8 * XS_STRIDE + k0 + 4]);
        const float2* wrow = wsp + (ks * 4 + tig) * WSP_STRIDE + warp_n * 64 + gid;
#pragma unroll
        for (int j = 0; j < 8; ++j) {
            float2 b = wrow[j * 8];
            asm volatile(
                "mma.sync.aligned.m16n8k8.row.col.f32.tf32.tf32.f32 "
                "{%0,%1,%2,%3}, {%4,%5,%6,%7}, {%8,%9}, {%0,%1,%2,%3};"
                : "+f"(acc[j][0]), "+f"(acc[j][1]), "+f"(acc[j][2]), "+f"(acc[j][3])
                : "r"(a0), "r"(a1), "r"(a2), "r"(a3),
                  "r"(__float_as_uint(b.x)), "r"(__float_as_uint(b.y)));
        }
    }

    // Epilogue: scale row by dinv, convert to fp16, store half2.
    int rA = row0 + warp_m * 16 + gid;
    int rB = rA + 8;
    int cb = warp_n * 64 + tig * 2;
    float sA = (rA < n) ? g_dinv[rA] : 0.0f;
    float sB = (rB < n) ? g_dinv[rB] : 0.0f;
#pragma unroll
    for (int j = 0; j < 8; ++j) {
        int c = cb + j * 8;
        if (rA < n) *(__half2*)&Y[(size_t)rA * D + c] =
            __floats2half2_rn(acc[j][0] * sA, acc[j][1] * sA);
        if (rB < n) *(__half2*)&Y[(size_t)rB * D + c] =
            __floats2half2_rn(acc[j][2] * sB, acc[j][3] * sB);
    }
}

// ---------------------------------------------------------------------------
// Gather: warp per destination node, fp16 source rows (256B each):
// out[c] = dinv[c] * ( sum_{r in in(c)} hs[r] + hs[c] ) + b   (fp32 accum)
// Each lane covers 4 columns via one 8-byte load (2x half2).
// ---------------------------------------------------------------------------
__global__ __launch_bounds__(256) void gather_kernel(
    const __half* __restrict__ h, const float* __restrict__ b,
    float* __restrict__ out, int n, int E) {
    int node = blockIdx.x * 8 + (threadIdx.x >> 5);
    if (node >= n) return;
    int lane = threadIdx.x & 31;

    float dc = g_dinv[node];
    const uint2* hh = (const uint2*)h;       // 32 uint2 per 128-col row

    int j    = g_off[node];
    int eend = (node + 1 < n) ? g_off[node + 1] : E;

    float4 acc = make_float4(0.f, 0.f, 0.f, 0.f);

    while (j < eend) {
        int cnt = min(32, eend - j);
        int r = 0;
        if (lane < cnt) r = g_src[j + lane];
#pragma unroll 4
        for (int k = 0; k < cnt; ++k) {
            int rk = __shfl_sync(0xffffffffu, r, k);
            uint2 hv = hh[(size_t)rk * 32 + lane];
            float2 f0 = __half22float2(*(const __half2*)&hv.x);
            float2 f1 = __half22float2(*(const __half2*)&hv.y);
            acc.x += f0.x;
            acc.y += f0.y;
            acc.z += f1.x;
            acc.w += f1.y;
        }
        j += cnt;
    }

    // self-loop + scale by dinv + bias
    uint2 hv = hh[(size_t)node * 32 + lane];
    float2 f0 = __half22float2(*(const __half2*)&hv.x);
    float2 f1 = __half22float2(*(const __half2*)&hv.y);
    float4 bv = ((const float4*)b)[lane];
    float4 o;
    o.x = fmaf(dc, acc.x + f0.x, bv.x);
    o.y = fmaf(dc, acc.y + f0.y, bv.y);
    o.z = fmaf(dc, acc.z + f1.x, bv.z);
    o.w = fmaf(dc, acc.w + f1.y, bv.w);
    ((float4*)out)[(size_t)node * 32 + lane] = o;
}

// ---------------------------------------------------------------------------
extern "C" void kernel_launch(void* const* d_in, const int* in_sizes, int n_in,
                              void* d_out, int out_size) {
    const float* x  = (const float*)d_in[0];
    const int*   ei = (const int*)d_in[1];
    const float* W1 = (const float*)d_in[2];
    const float* b1 = (const float*)d_in[3];
    const float* W2 = (const float*)d_in[4];
    const float* b2 = (const float*)d_in[5];
    float* out = (float*)d_out;

    int n = in_sizes[0] / D;
    int E = in_sizes[1] / 2;
    const int* row = ei;        // edge_index[0]
    const int* col = ei + E;    // edge_index[1]

    __half* hA;  cudaGetSymbolAddress((void**)&hA,  g_hA);
    __half* hB;  cudaGetSymbolAddress((void**)&hB,  g_hB);
    float* agg;  cudaGetSymbolAddress((void**)&agg, g_agg);
    float2* wp;  cudaGetSymbolAddress((void**)&wp,  g_wpack);
    int* degp;   cudaGetSymbolAddress((void**)&degp, g_deg);

    cudaFuncSetAttribute(gemm_tf32_kernel,
                         cudaFuncAttributeMaxDynamicSharedMemorySize,
                         GEMM_SMEM_BYTES);

    int eb256 = (E + 255) / 256;
    int nb1k  = (n + 1023) / 1024;
    int gblk  = (n + 127) / 128;
    int gath  = (n + 7) / 8;

    // normalization + CSR build + weight pre-pack (once per call)
    cudaMemsetAsync(degp, 0, (size_t)n * sizeof(int));
    count_deg_kernel<<<eb256, 256>>>(col, E);
    pack_w_kernel<<<64, 256>>>(W1, W2);
    scan1_kernel<<<nb1k, 1024>>>(n);     // also computes dinv
    scan2_kernel<<<1, 128>>>(nb1k);
    scan3_kernel<<<nb1k, 1024>>>(n);
    fill_kernel<<<eb256, 256>>>(row, col, E);

    // layer 1: hA = fp16( dinv .* (x @ W1) );  agg = gather(hA) + b1
    gemm_tf32_kernel<<<gblk, 512, GEMM_SMEM_BYTES>>>(x, wp, hA, n, 0);
    gather_kernel<<<gath, 256>>>(hA, b1, agg, n, E);

    // layer 2: hB = fp16( dinv .* (relu(agg) @ W2) );  out = gather(hB) + b2
    gemm_tf32_kernel<<<gblk, 512, GEMM_SMEM_BYTES>>>(agg, wp + 8192, hB, n, 1);
    gather_kernel<<<gath, 256>>>(hB, b2, out, n, E);
}